// round 1
// baseline (speedup 1.0000x reference)
#include <cuda_runtime.h>
#include <cstdint>
#include <math.h>

#define B_    64
#define C_    256
#define T_    1024
#define H_    512
#define S_TOT 192
#define S_RX0 64
#define BETA  0.9f
#define THR   0.75f
#define LCAP  120      // per-timestep active-index list capacity (padded to mult of 8)
#define TCH   16       // timesteps per staged chunk in scan kernel
#define OB    64       // output channels per scan CTA

// ---- output layout (flattened tuple, float32) ----
#define OUT_D  0
#define OUT_A  (B_*H_)
#define OUT_E  (2*B_*H_)
#define OUT_RX (3*B_*H_)
#define OUT_PX (3*B_*H_ + B_*2*C_*T_)

// ---- static device scratch (no allocations) ----
__device__ uint4          g_idx_w [S_TOT * T_ * (LCAP/8)];  // 15 uint4 (=120 u16) per (s,t)
__device__ unsigned short g_cnt   [S_TOT * T_];             // padded active count per (s,t)
__device__ unsigned int   g_trace [128 * C_ * 32];          // rx spike bits, [rb][c][t/32]
__device__ int            g_spkcnt[S_TOT * C_];             // spike count per (s,c)
__device__ float          g_feat  [3 * B_ * C_];            // layernormed features

// ============================================================================
// K1: build per-timestep active-channel index lists (ballot compaction)
// grid: 192*32 CTAs, 256 threads. CTA = (s, 32-timestep tile)
// ============================================================================
__global__ void k1_pack(const float* __restrict__ tx, const float* __restrict__ rxsp)
{
    __shared__ float tile[256 * 33];
    __shared__ __align__(16) unsigned short lists[32 * LCAP];
    __shared__ int cnts[32];

    const int s  = blockIdx.x >> 5;
    const int t0 = (blockIdx.x & 31) * 32;
    const float* base = (s < S_RX0) ? (tx + (size_t)s * C_ * T_)
                                    : (rxsp + (size_t)(s - S_RX0) * C_ * T_);
    const int w = threadIdx.x >> 5, l = threadIdx.x & 31;

    // coalesced load [256 c][32 t] (pad 33 to avoid bank conflicts)
    #pragma unroll 4
    for (int i = 0; i < 32; i++) {
        int c = i * 8 + w;
        tile[c * 33 + l] = base[(size_t)c * T_ + t0 + l];
    }
    __syncthreads();

    // warp w compacts timesteps w*4 .. w*4+3
    for (int tt = w * 4; tt < w * 4 + 4; tt++) {
        int cnt = 0;
        #pragma unroll
        for (int g = 0; g < 8; g++) {
            float v = tile[(g * 32 + l) * 33 + tt];
            unsigned m = __ballot_sync(0xffffffffu, v > 0.5f);
            if (v > 0.5f) {
                int pos = cnt + __popc(m & ((1u << l) - 1u));
                if (pos < LCAP) lists[tt * LCAP + pos] = (unsigned short)(g * 32 + l);
            }
            cnt += __popc(m);
        }
        if (cnt > 112) cnt = 112;               // astronomically unlikely
        int padded = (cnt + 7) & ~7;
        if (l < padded - cnt) lists[tt * LCAP + cnt + l] = 256;  // zero-column pad
        if (l == 0) cnts[tt] = padded;
    }
    __syncthreads();

    uint4* dst = g_idx_w + (size_t)(s * T_ + t0) * (LCAP/8);
    const uint4* srcw = (const uint4*)lists;
    for (int i = threadIdx.x; i < 32 * (LCAP/8); i += 256) dst[i] = srcw[i];
    if (threadIdx.x < 32)
        g_cnt[s * T_ + t0 + threadIdx.x] = (unsigned short)cnts[threadIdx.x];
}

// ============================================================================
// K2: fused sparse-mix + LIF scan. CTA = (s, 64-channel block), 64 threads.
// W rows cached in smem (transposed, stride 65, +zero row for pad idx 256).
// ============================================================================
__global__ void k2_scan(const float* __restrict__ W_tx, const float* __restrict__ b_tx,
                        const float* __restrict__ W_rx, const float* __restrict__ b_rx)
{
    extern __shared__ unsigned char smem_raw[];
    float*          W_sh   = (float*)smem_raw;                         // 257*65*4 = 66820 B
    unsigned short* lists  = (unsigned short*)(smem_raw + 66832);      // 16*120*2 = 3840 B
    unsigned short* cnt_sh = (unsigned short*)(smem_raw + 70672);      // 16*2 B

    const int tid = threadIdx.x;
    const int s   = blockIdx.x >> 2;
    const int o0  = (blockIdx.x & 3) * OB;
    const bool is_rx = (s >= S_RX0);
    const float* W = is_rx ? W_rx : W_tx;
    const float* bb = is_rx ? b_rx : b_tx;

    // load W rows [o0, o0+64) transposed into smem: W_sh[c*65 + o_local]
    for (int r = 0; r < OB; r++) {
        #pragma unroll
        for (int cc = tid; cc < C_; cc += OB)
            W_sh[cc * 65 + r] = W[(size_t)(o0 + r) * C_ + cc];
    }
    W_sh[256 * 65 + tid] = 0.0f;   // zero row (pad index 256)
    if (tid == 0) W_sh[256 * 65 + 64] = 0.0f;
    const float bias = bb[o0 + tid];
    const float* Wt = W_sh + tid;

    float mem = 0.0f, spk = 0.0f;
    unsigned int word = 0;
    int scount = 0;
    const unsigned trace_base = is_rx ? ((unsigned)(s - S_RX0) * C_ + o0 + tid) * 32u : 0u;

    for (int ch = 0; ch < T_ / TCH; ++ch) {
        const int t0 = ch * TCH;
        __syncthreads();
        {
            const uint4* src = g_idx_w + (size_t)(s * T_ + t0) * (LCAP/8);
            uint4* dstl = (uint4*)lists;
            #pragma unroll
            for (int i = tid; i < TCH * (LCAP/8); i += OB) dstl[i] = src[i];
            if (tid < TCH) cnt_sh[tid] = g_cnt[s * T_ + t0 + tid];
        }
        __syncthreads();

        #pragma unroll 1
        for (int tt = 0; tt < TCH; ++tt) {
            const int t = t0 + tt;
            const int n8 = cnt_sh[tt] >> 3;
            const uint4* lw = (const uint4*)(lists + tt * LCAP);
            float a0 = bias, a1 = 0.0f, a2 = 0.0f, a3 = 0.0f;
            #pragma unroll 1
            for (int j = 0; j < n8; ++j) {
                uint4 v = lw[j];
                a0 += Wt[(v.x & 0xffffu) * 65]; a1 += Wt[(v.x >> 16) * 65];
                a2 += Wt[(v.y & 0xffffu) * 65]; a3 += Wt[(v.y >> 16) * 65];
                a0 += Wt[(v.z & 0xffffu) * 65]; a1 += Wt[(v.z >> 16) * 65];
                a2 += Wt[(v.w & 0xffffu) * 65]; a3 += Wt[(v.w >> 16) * 65];
            }
            const float acc = (a0 + a1) + (a2 + a3);
            mem = BETA * mem + acc - spk * THR;
            const bool sp = (mem - THR) > 0.0f;
            word |= (sp ? 1u : 0u) << (t & 31);
            scount += sp ? 1 : 0;
            spk = sp ? 1.0f : 0.0f;
            if ((t & 31) == 31) {
                if (is_rx) g_trace[trace_base + (t >> 5)] = word;
                word = 0;
            }
        }
    }
    g_spkcnt[s * C_ + o0 + tid] = scount;
}

// ============================================================================
// K3: expand rx spike bits -> float32 trace in d_out (LUT nibble expansion)
// grid 4096 CTAs, 256 threads; warp per (rb,c) row of 1024 timesteps
// ============================================================================
__global__ void k3_expand(float* __restrict__ out)
{
    __shared__ float4 lut[16];
    if (threadIdx.x < 16)
        lut[threadIdx.x] = make_float4((float)(threadIdx.x & 1), (float)((threadIdx.x >> 1) & 1),
                                       (float)((threadIdx.x >> 2) & 1), (float)((threadIdx.x >> 3) & 1));
    __syncthreads();

    const int row = blockIdx.x * 8 + (threadIdx.x >> 5);   // 0..32767
    const int l   = threadIdx.x & 31;
    const unsigned word = g_trace[(size_t)row * 32 + l];
    float4* dst = (float4*)(out + OUT_RX + (size_t)row * T_);
    #pragma unroll
    for (int k = 0; k < 8; k++) {
        const int t4   = k * 32 + l;         // float4 index within the row
        const unsigned wsrc = __shfl_sync(0xffffffffu, word, t4 >> 3);
        const unsigned nib  = (wsrc >> ((t4 & 7) * 4)) & 0xFu;
        dst[t4] = lut[nib];
    }
}

// ============================================================================
// K4a: features + layernorm + spike_proxy. CTA per batch b, 256 threads (=c)
// ============================================================================
__device__ __forceinline__ float blk_sum(float v, float* red, int c)
{
    red[c] = v; __syncthreads();
    #pragma unroll
    for (int off = 128; off > 0; off >>= 1) {
        if (c < off) red[c] += red[c + off];
        __syncthreads();
    }
    float s = red[0]; __syncthreads();
    return s;
}

__global__ void k4a_feat(float* __restrict__ out)
{
    __shared__ float red[256];
    const int b = blockIdx.x, c = threadIdx.x;
    const int cd = g_spkcnt[b * C_ + c];
    const int cl = g_spkcnt[(S_RX0 + b * 2 + 0) * C_ + c];
    const int cr = g_spkcnt[(S_RX0 + b * 2 + 1) * C_ + c];

    out[OUT_PX + (size_t)(b * 2 + 0) * C_ + c] = (float)cl;
    out[OUT_PX + (size_t)(b * 2 + 1) * C_ + c] = (float)cr;

    float f[3];
    f[0] = (float)cd        * (1.0f / 1024.0f);
    f[1] = (float)(cl - cr) * (1.0f / 1024.0f);
    f[2] = (float)(cl + cr) * (1.0f / 1024.0f);

    #pragma unroll
    for (int typ = 0; typ < 3; typ++) {
        const float mu = blk_sum(f[typ], red, c) * (1.0f / 256.0f);
        const float xc = f[typ] - mu;
        const float var = blk_sum(xc * xc, red, c) * (1.0f / 256.0f);
        g_feat[(typ * B_ + b) * C_ + c] = xc / sqrtf(var + 1e-5f);
    }
}

// ============================================================================
// K4b: heads — [64x256]@[256x512]^T + bias, gain, residual, relu.
// grid 3*64 CTAs (8 h per CTA, warp per h), 256 threads, 64KB dyn smem.
// ============================================================================
__global__ void k4b_head(const float* __restrict__ Wd, const float* __restrict__ bd,
                         const float* __restrict__ Wa, const float* __restrict__ ba,
                         const float* __restrict__ We, const float* __restrict__ be,
                         const float* __restrict__ base_d, const float* __restrict__ base_a,
                         const float* __restrict__ base_e,
                         const float* __restrict__ gd, const float* __restrict__ ga,
                         const float* __restrict__ ge,
                         float* __restrict__ out)
{
    extern __shared__ float x_sh[];   // 64*256 floats
    const int typ = blockIdx.x >> 6;
    const int h0  = (blockIdx.x & 63) * 8;

    const float* feat = g_feat + (size_t)typ * B_ * C_;
    for (int i = threadIdx.x; i < B_ * C_; i += 256) x_sh[i] = feat[i];
    __syncthreads();

    const float* Wm   = (typ == 0) ? Wd : (typ == 1) ? Wa : We;
    const float* bm   = (typ == 0) ? bd : (typ == 1) ? ba : be;
    const float* bsp  = (typ == 0) ? base_d : (typ == 1) ? base_a : base_e;
    const float  g    = (typ == 0) ? *gd : (typ == 1) ? *ga : *ge;
    const float  sg   = 0.3f / (1.0f + expf(-g));
    const size_t ooff = (typ == 0) ? OUT_D : (typ == 1) ? OUT_A : OUT_E;

    const int lane = threadIdx.x & 31;
    const int h    = h0 + (threadIdx.x >> 5);

    const float4* wrow = (const float4*)(Wm + (size_t)h * C_);
    const float4 w0 = wrow[lane * 2];
    const float4 w1 = wrow[lane * 2 + 1];
    const float  bh = bm[h];

    for (int b = 0; b < B_; b++) {
        const float4* xb = (const float4*)(x_sh + b * C_ + lane * 8);
        const float4 x0 = xb[0], x1 = xb[1];
        float p = w0.x * x0.x + w0.y * x0.y + w0.z * x0.z + w0.w * x0.w
                + w1.x * x1.x + w1.y * x1.y + w1.z * x1.z + w1.w * x1.w;
        #pragma unroll
        for (int off = 16; off > 0; off >>= 1)
            p += __shfl_xor_sync(0xffffffffu, p, off);
        if (lane == 0) {
            const float r = p + bh;
            const float v = bsp[(size_t)b * H_ + h] + sg * r;
            out[ooff + (size_t)b * H_ + h] = v > 0.0f ? v : 0.0f;
        }
    }
}

// ============================================================================
extern "C" void kernel_launch(void* const* d_in, const int* in_sizes, int n_in,
                              void* d_out, int out_size)
{
    const float* tx    = (const float*)d_in[0];
    const float* rxsp  = (const float*)d_in[1];
    const float* bsd   = (const float*)d_in[2];
    const float* bsa   = (const float*)d_in[3];
    const float* bse   = (const float*)d_in[4];
    const float* W_tx  = (const float*)d_in[5];
    const float* b_tx  = (const float*)d_in[6];
    const float* W_rx  = (const float*)d_in[7];
    const float* b_rx  = (const float*)d_in[8];
    const float* Wd    = (const float*)d_in[9];
    const float* bd    = (const float*)d_in[10];
    const float* Wa    = (const float*)d_in[11];
    const float* ba    = (const float*)d_in[12];
    const float* We    = (const float*)d_in[13];
    const float* be    = (const float*)d_in[14];
    const float* gd    = (const float*)d_in[15];
    const float* ga    = (const float*)d_in[16];
    const float* ge    = (const float*)d_in[17];
    float* out = (float*)d_out;

    static bool attr_set = false;
    if (!attr_set) {
        cudaFuncSetAttribute(k2_scan, cudaFuncAttributeMaxDynamicSharedMemorySize, 70720);
        cudaFuncSetAttribute(k4b_head, cudaFuncAttributeMaxDynamicSharedMemorySize, 65536);
        attr_set = true;
    }

    k1_pack<<<S_TOT * 32, 256>>>(tx, rxsp);
    k2_scan<<<S_TOT * 4, OB, 70720>>>(W_tx, b_tx, W_rx, b_rx);
    k3_expand<<<4096, 256>>>(out);
    k4a_feat<<<B_, 256>>>(out);
    k4b_head<<<3 * 64, 256, 65536>>>(Wd, bd, Wa, ba, We, be, bsd, bsa, bse, gd, ga, ge, out);
}

// round 2
// speedup vs baseline: 2.0835x; 2.0835x over previous
#include <cuda_runtime.h>
#include <cstdint>
#include <math.h>

#define B_    64
#define C_    256
#define T_    1024
#define H_    512
#define S_TOT 192
#define S_RX0 64
#define BETA  0.9f
#define THR   0.75f
#define LCAP  120      // per-timestep active-index list capacity (u16, padded to mult of 8)
#define TT    128      // timesteps per k2a CTA tile
#define OB    64       // output channels per k2a CTA

// ---- output layout (flattened tuple, float32) ----
#define OUT_D  0
#define OUT_A  (B_*H_)
#define OUT_E  (2*B_*H_)
#define OUT_RX (3*B_*H_)
#define OUT_PX (3*B_*H_ + B_*2*C_*T_)

// ---- static device scratch (no allocations) ----
__device__ uint4          g_idx_w [S_TOT * T_ * (LCAP/8)];  // 15 uint4 (=120 u16) per (s,t)
__device__ unsigned short g_cnt   [S_TOT * T_];             // padded active count per (s,t)
__device__ float          g_acc   [(size_t)S_TOT * T_ * C_];// mixed (pre-bias), [s][t][c]
__device__ unsigned int   g_trace [128 * C_ * 32];          // rx spike bits, [rb][c][t/32]
__device__ int            g_spkcnt[S_TOT * C_];             // spike count per (s,c)
__device__ float          g_feat  [3 * B_ * C_];            // layernormed features

// ============================================================================
// K1: build per-timestep active-channel index lists (ballot compaction).
// Indices stored PRE-MULTIPLIED by 33 (float2 stride of W_sh row).
// grid: 192*32 CTAs, 256 threads. CTA = (s, 32-timestep tile)
// ============================================================================
__global__ void k1_pack(const float* __restrict__ tx, const float* __restrict__ rxsp)
{
    __shared__ float tile[256 * 33];
    __shared__ __align__(16) unsigned short lists[32 * LCAP];
    __shared__ int cnts[32];

    const int s  = blockIdx.x >> 5;
    const int t0 = (blockIdx.x & 31) * 32;
    const float* base = (s < S_RX0) ? (tx + (size_t)s * C_ * T_)
                                    : (rxsp + (size_t)(s - S_RX0) * C_ * T_);
    const int w = threadIdx.x >> 5, l = threadIdx.x & 31;

    #pragma unroll 4
    for (int i = 0; i < 32; i++) {
        int c = i * 8 + w;
        tile[c * 33 + l] = base[(size_t)c * T_ + t0 + l];
    }
    __syncthreads();

    for (int tt = w * 4; tt < w * 4 + 4; tt++) {
        int cnt = 0;
        #pragma unroll
        for (int g = 0; g < 8; g++) {
            float v = tile[(g * 32 + l) * 33 + tt];
            unsigned m = __ballot_sync(0xffffffffu, v > 0.5f);
            if (v > 0.5f) {
                int pos = cnt + __popc(m & ((1u << l) - 1u));
                if (pos < LCAP) lists[tt * LCAP + pos] = (unsigned short)((g * 32 + l) * 33);
            }
            cnt += __popc(m);
        }
        if (cnt > 112) cnt = 112;               // astronomically unlikely
        int padded = (cnt + 7) & ~7;
        if (l < padded - cnt) lists[tt * LCAP + cnt + l] = (unsigned short)(256 * 33); // zero row
        if (l == 0) cnts[tt] = padded;
    }
    __syncthreads();

    uint4* dst = g_idx_w + (size_t)(s * T_ + t0) * (LCAP/8);
    const uint4* srcw = (const uint4*)lists;
    for (int i = threadIdx.x; i < 32 * (LCAP/8); i += 256) dst[i] = srcw[i];
    if (threadIdx.x < 32)
        g_cnt[s * T_ + t0 + threadIdx.x] = (unsigned short)cnts[threadIdx.x];
}

// ============================================================================
// K2a: PARALLEL sparse mix: acc[s][t][c] = sum_{active j} W[c][j]  (no bias).
// CTA = (s, 64-out block, 128-t tile), 256 threads = 8 warps, warp = 16 t's.
// W block transposed in smem stride 66 (33 float2), +zero row for pad idx.
// Each lane accumulates 2 outputs via float2 LDS.
// ============================================================================
__global__ void k2a_mix(const float* __restrict__ W_tx, const float* __restrict__ W_rx)
{
    extern __shared__ unsigned char smem_raw[];
    float*          W_sh   = (float*)smem_raw;                        // 257*66*4 = 67848 B
    unsigned short* lists  = (unsigned short*)(smem_raw + 67856);     // 128*120*2 = 30720 B
    unsigned short* cnt_sh = (unsigned short*)(smem_raw + 98576);     // 128*2 B

    const int tid = threadIdx.x;
    const int s   = blockIdx.z;
    const int o0  = blockIdx.y * OB;
    const int t0  = blockIdx.x * TT;
    const float* W = (s < S_RX0) ? W_tx : W_rx;

    // W rows [o0, o0+64) transposed: W_sh[c*66 + r]
    #pragma unroll 4
    for (int idx = tid; idx < OB * C_; idx += 256) {
        int r = idx >> 8, c = idx & 255;
        W_sh[c * 66 + r] = W[(size_t)(o0 + r) * C_ + c];
    }
    if (tid < 66) W_sh[256 * 66 + tid] = 0.0f;   // zero row (pad index)

    {
        const uint4* src = g_idx_w + (size_t)(s * T_ + t0) * (LCAP/8);
        uint4* dstl = (uint4*)lists;
        #pragma unroll 2
        for (int i = tid; i < TT * (LCAP/8); i += 256) dstl[i] = src[i];
        if (tid < TT) cnt_sh[tid] = g_cnt[s * T_ + t0 + tid];
    }
    __syncthreads();

    const int w = tid >> 5, lane = tid & 31;
    const float2* Wt2 = (const float2*)W_sh + lane;

    #pragma unroll 1
    for (int tslot = 0; tslot < TT / 8; ++tslot) {
        const int tt = w * (TT / 8) + tslot;
        const int n8 = cnt_sh[tt] >> 3;
        const uint4* lw = (const uint4*)(lists + tt * LCAP);
        float a0x = 0.f, a0y = 0.f, a1x = 0.f, a1y = 0.f;
        float a2x = 0.f, a2y = 0.f, a3x = 0.f, a3y = 0.f;
        #pragma unroll 1
        for (int j = 0; j < n8; ++j) {
            uint4 v = lw[j];
            float2 w0 = Wt2[v.x & 0xffffu];  a0x += w0.x; a0y += w0.y;
            float2 w1 = Wt2[v.x >> 16];      a1x += w1.x; a1y += w1.y;
            float2 w2 = Wt2[v.y & 0xffffu];  a2x += w2.x; a2y += w2.y;
            float2 w3 = Wt2[v.y >> 16];      a3x += w3.x; a3y += w3.y;
            float2 w4 = Wt2[v.z & 0xffffu];  a0x += w4.x; a0y += w4.y;
            float2 w5 = Wt2[v.z >> 16];      a1x += w5.x; a1y += w5.y;
            float2 w6 = Wt2[v.w & 0xffffu];  a2x += w6.x; a2y += w6.y;
            float2 w7 = Wt2[v.w >> 16];      a3x += w7.x; a3y += w7.y;
        }
        float2 r;
        r.x = (a0x + a1x) + (a2x + a3x);
        r.y = (a0y + a1y) + (a2y + a3y);
        *(float2*)(g_acc + (size_t)(s * T_ + t0 + tt) * C_ + o0 + 2 * lane) = r;
    }
}

// ============================================================================
// K2b: LIF recurrence only. Thread per (s,c), 1024 steps, loads batched x32.
// grid 384 CTAs x 128 threads.
// ============================================================================
__global__ void k2b_scan(const float* __restrict__ b_tx, const float* __restrict__ b_rx)
{
    const int gid = blockIdx.x * 128 + threadIdx.x;   // 0..49151
    const int s = gid >> 8, c = gid & 255;
    const bool is_rx = (s >= S_RX0);
    const float bias = is_rx ? b_rx[c] : b_tx[c];
    const float* ap = g_acc + (size_t)s * T_ * C_ + c;
    const unsigned tb = is_rx ? ((unsigned)(s - S_RX0) * C_ + c) * 32u : 0u;

    float m = 0.0f, sub = 0.0f;
    int cnt = 0;

    #pragma unroll 1
    for (int t32 = 0; t32 < 32; ++t32) {
        float av[32];
        #pragma unroll
        for (int k = 0; k < 32; ++k)
            av[k] = ap[(size_t)(t32 * 32 + k) * C_];
        unsigned word = 0;
        #pragma unroll
        for (int k = 0; k < 32; ++k) {
            m = BETA * m + (av[k] + bias) - sub;
            const bool sp = m > THR;
            sub = sp ? THR : 0.0f;
            word |= (sp ? 1u : 0u) << k;
        }
        if (is_rx) g_trace[tb + t32] = word;
        cnt += __popc(word);
    }
    g_spkcnt[s * C_ + c] = cnt;
}

// ============================================================================
// K3: expand rx spike bits -> float32 trace in d_out (LUT nibble expansion)
// ============================================================================
__global__ void k3_expand(float* __restrict__ out)
{
    __shared__ float4 lut[16];
    if (threadIdx.x < 16)
        lut[threadIdx.x] = make_float4((float)(threadIdx.x & 1), (float)((threadIdx.x >> 1) & 1),
                                       (float)((threadIdx.x >> 2) & 1), (float)((threadIdx.x >> 3) & 1));
    __syncthreads();

    const int row = blockIdx.x * 8 + (threadIdx.x >> 5);   // 0..32767
    const int l   = threadIdx.x & 31;
    const unsigned word = g_trace[(size_t)row * 32 + l];
    float4* dst = (float4*)(out + OUT_RX + (size_t)row * T_);
    #pragma unroll
    for (int k = 0; k < 8; k++) {
        const int t4   = k * 32 + l;
        const unsigned wsrc = __shfl_sync(0xffffffffu, word, t4 >> 3);
        const unsigned nib  = (wsrc >> ((t4 & 7) * 4)) & 0xFu;
        dst[t4] = lut[nib];
    }
}

// ============================================================================
// K4a: features + layernorm + spike_proxy. CTA per batch b, 256 threads (=c)
// ============================================================================
__device__ __forceinline__ float blk_sum(float v, float* red, int c)
{
    red[c] = v; __syncthreads();
    #pragma unroll
    for (int off = 128; off > 0; off >>= 1) {
        if (c < off) red[c] += red[c + off];
        __syncthreads();
    }
    float s = red[0]; __syncthreads();
    return s;
}

__global__ void k4a_feat(float* __restrict__ out)
{
    __shared__ float red[256];
    const int b = blockIdx.x, c = threadIdx.x;
    const int cd = g_spkcnt[b * C_ + c];
    const int cl = g_spkcnt[(S_RX0 + b * 2 + 0) * C_ + c];
    const int cr = g_spkcnt[(S_RX0 + b * 2 + 1) * C_ + c];

    out[OUT_PX + (size_t)(b * 2 + 0) * C_ + c] = (float)cl;
    out[OUT_PX + (size_t)(b * 2 + 1) * C_ + c] = (float)cr;

    float f[3];
    f[0] = (float)cd        * (1.0f / 1024.0f);
    f[1] = (float)(cl - cr) * (1.0f / 1024.0f);
    f[2] = (float)(cl + cr) * (1.0f / 1024.0f);

    #pragma unroll
    for (int typ = 0; typ < 3; typ++) {
        const float mu = blk_sum(f[typ], red, c) * (1.0f / 256.0f);
        const float xc = f[typ] - mu;
        const float var = blk_sum(xc * xc, red, c) * (1.0f / 256.0f);
        g_feat[(typ * B_ + b) * C_ + c] = xc / sqrtf(var + 1e-5f);
    }
}

// ============================================================================
// K4b: heads — [64x256]@[256x512]^T + bias, gain, residual, relu.
// ============================================================================
__global__ void k4b_head(const float* __restrict__ Wd, const float* __restrict__ bd,
                         const float* __restrict__ Wa, const float* __restrict__ ba,
                         const float* __restrict__ We, const float* __restrict__ be,
                         const float* __restrict__ base_d, const float* __restrict__ base_a,
                         const float* __restrict__ base_e,
                         const float* __restrict__ gd, const float* __restrict__ ga,
                         const float* __restrict__ ge,
                         float* __restrict__ out)
{
    extern __shared__ float x_sh[];   // 64*256 floats
    const int typ = blockIdx.x >> 6;
    const int h0  = (blockIdx.x & 63) * 8;

    const float* feat = g_feat + (size_t)typ * B_ * C_;
    for (int i = threadIdx.x; i < B_ * C_; i += 256) x_sh[i] = feat[i];
    __syncthreads();

    const float* Wm   = (typ == 0) ? Wd : (typ == 1) ? Wa : We;
    const float* bm   = (typ == 0) ? bd : (typ == 1) ? ba : be;
    const float* bsp  = (typ == 0) ? base_d : (typ == 1) ? base_a : base_e;
    const float  g    = (typ == 0) ? *gd : (typ == 1) ? *ga : *ge;
    const float  sg   = 0.3f / (1.0f + expf(-g));
    const size_t ooff = (typ == 0) ? OUT_D : (typ == 1) ? OUT_A : OUT_E;

    const int lane = threadIdx.x & 31;
    const int h    = h0 + (threadIdx.x >> 5);

    const float4* wrow = (const float4*)(Wm + (size_t)h * C_);
    const float4 w0 = wrow[lane * 2];
    const float4 w1 = wrow[lane * 2 + 1];
    const float  bh = bm[h];

    for (int b = 0; b < B_; b++) {
        const float4* xb = (const float4*)(x_sh + b * C_ + lane * 8);
        const float4 x0 = xb[0], x1 = xb[1];
        float p = w0.x * x0.x + w0.y * x0.y + w0.z * x0.z + w0.w * x0.w
                + w1.x * x1.x + w1.y * x1.y + w1.z * x1.z + w1.w * x1.w;
        #pragma unroll
        for (int off = 16; off > 0; off >>= 1)
            p += __shfl_xor_sync(0xffffffffu, p, off);
        if (lane == 0) {
            const float r = p + bh;
            const float v = bsp[(size_t)b * H_ + h] + sg * r;
            out[ooff + (size_t)b * H_ + h] = v > 0.0f ? v : 0.0f;
        }
    }
}

// ============================================================================
extern "C" void kernel_launch(void* const* d_in, const int* in_sizes, int n_in,
                              void* d_out, int out_size)
{
    const float* tx    = (const float*)d_in[0];
    const float* rxsp  = (const float*)d_in[1];
    const float* bsd   = (const float*)d_in[2];
    const float* bsa   = (const float*)d_in[3];
    const float* bse   = (const float*)d_in[4];
    const float* W_tx  = (const float*)d_in[5];
    const float* b_tx  = (const float*)d_in[6];
    const float* W_rx  = (const float*)d_in[7];
    const float* b_rx  = (const float*)d_in[8];
    const float* Wd    = (const float*)d_in[9];
    const float* bd    = (const float*)d_in[10];
    const float* Wa    = (const float*)d_in[11];
    const float* ba    = (const float*)d_in[12];
    const float* We    = (const float*)d_in[13];
    const float* be    = (const float*)d_in[14];
    const float* gd    = (const float*)d_in[15];
    const float* ga    = (const float*)d_in[16];
    const float* ge    = (const float*)d_in[17];
    float* out = (float*)d_out;

    static bool attr_set = false;
    if (!attr_set) {
        cudaFuncSetAttribute(k2a_mix, cudaFuncAttributeMaxDynamicSharedMemorySize, 98832);
        cudaFuncSetAttribute(k4b_head, cudaFuncAttributeMaxDynamicSharedMemorySize, 65536);
        attr_set = true;
    }

    k1_pack<<<S_TOT * 32, 256>>>(tx, rxsp);
    k2a_mix<<<dim3(T_ / TT, C_ / OB, S_TOT), 256, 98832>>>(W_tx, W_rx);
    k2b_scan<<<384, 128>>>(b_tx, b_rx);
    k3_expand<<<4096, 256>>>(out);
    k4a_feat<<<B_, 256>>>(out);
    k4b_head<<<3 * 64, 256, 65536>>>(Wd, bd, Wa, ba, We, be, bsd, bsa, bse, gd, ga, ge, out);
}